// round 16
// baseline (speedup 1.0000x reference)
#include <cuda_runtime.h>
#include <cuda_bf16.h>
#include <cstdint>

// ====================== constants ======================
static constexpr int D         = 64;
static constexpr int K         = 512;
static constexpr int TILE_ROWS = 32;    // rows per row-tile
static constexpr int ROW_TILES = 8;     // row-tiles per CTA (B loaded once)
static constexpr int THREADS   = 512;   // 16 warps: 1 row-group x 16 col-groups (32x32 tiles)

// Padded smem rows: 72 bf16 = 144 bytes. Row step = 36 words == 4 (mod 32)
// -> ldmatrix 16B fetches from 8 consecutive rows hit distinct bank groups.
static constexpr int ROW_BYTES = 144;

// smem layout (bytes) — A/xsq/rsum double-buffered
static constexpr int SMEM_A0    = 0;                          // 32 * 144 = 4608
static constexpr int SMEM_A1    = 4608;
static constexpr int SMEM_B     = 9216;                       // 512 * 144 = 73728
static constexpr int SMEM_CSQ   = 82944;                      // 512 * 4   = 2048
static constexpr int SMEM_XSQ0  = 84992;                      // 32 * 4
static constexpr int SMEM_XSQ1  = 85120;
static constexpr int SMEM_RSUM0 = 85248;                      // 16 * 32 * 4 = 2048
static constexpr int SMEM_RSUM1 = 87296;
static constexpr int SMEM_TOTAL = 89344;                      // x2 CTAs = 178688 < 228K

// ====================== PTX helpers ======================
__device__ __forceinline__ uint32_t smem_u32(const void* p) {
    uint32_t a;
    asm("{ .reg .u64 t; cvta.to.shared.u64 t, %1; cvt.u32.u64 %0, t; }" : "=r"(a) : "l"(p));
    return a;
}

#define LDMATRIX_X4(r0, r1, r2, r3, addr) \
    asm volatile("ldmatrix.sync.aligned.m8n8.x4.shared.b16 {%0,%1,%2,%3}, [%4];" \
                 : "=r"(r0), "=r"(r1), "=r"(r2), "=r"(r3) : "r"(addr))

#define MMA_16816_BF16(c0, c1, c2, c3, a0, a1, a2, a3, b0, b1) \
    asm volatile("mma.sync.aligned.m16n8k16.row.col.f32.bf16.bf16.f32 " \
                 "{%0,%1,%2,%3}, {%4,%5,%6,%7}, {%8,%9}, {%0,%1,%2,%3};" \
                 : "+f"(c0), "+f"(c1), "+f"(c2), "+f"(c3) \
                 : "r"(a0), "r"(a1), "r"(a2), "r"(a3), "r"(b0), "r"(b1))

// convert 8 fp32 (2 float4) -> 4 bf16x2 packed words
__device__ __forceinline__ uint4 pack_bf16x8(float4 a, float4 b) {
    __nv_bfloat162 p0 = __floats2bfloat162_rn(a.x, a.y);
    __nv_bfloat162 p1 = __floats2bfloat162_rn(a.z, a.w);
    __nv_bfloat162 p2 = __floats2bfloat162_rn(b.x, b.y);
    __nv_bfloat162 p3 = __floats2bfloat162_rn(b.z, b.w);
    uint4 v;
    v.x = *reinterpret_cast<uint32_t*>(&p0);
    v.y = *reinterpret_cast<uint32_t*>(&p1);
    v.z = *reinterpret_cast<uint32_t*>(&p2);
    v.w = *reinterpret_cast<uint32_t*>(&p3);
    return v;
}

// ====================== main kernel ======================
__global__ __launch_bounds__(THREADS, 2)
void cluster_q_kernel(const float* __restrict__ x, const float* __restrict__ cen,
                      float* __restrict__ out) {
    extern __shared__ char smem[];
    const uint32_t sb = smem_u32(smem);
    const int tid  = threadIdx.x;
    const int lane = tid & 31;
    const int base_row0 = blockIdx.x * (TILE_ROWS * ROW_TILES);

    float* csq = reinterpret_cast<float*>(smem + SMEM_CSQ);

    // A-fill: threads 0..255 each own one 16B chunk (32 rows x 8 chunks)
    const int a_row = tid >> 3;
    const int a_c8  = tid & 7;
    const bool a_filler = (tid < TILE_ROWS * 8);

    // issue tile-0 x loads early (latency hides under B fill)
    float4 pa, pb;
    if (a_filler) {
        const float4* g = reinterpret_cast<const float4*>(
            x + (size_t)(base_row0 + a_row) * D + a_c8 * 8);
        pa = g[0]; pb = g[1];
    }

    // --- B: load fp32 centroids, convert to bf16, padded rows; fused c_sq (shfl) ---
    {
        const int c8 = tid & 7;
#pragma unroll
        for (int i = 0; i < 8; i++) {
            const int row = (tid >> 3) + i * 64;
            const float4* g = reinterpret_cast<const float4*>(cen + (size_t)row * D + c8 * 8);
            float4 a = g[0], b = g[1];
            float s = a.x * a.x + a.y * a.y + a.z * a.z + a.w * a.w
                    + b.x * b.x + b.y * b.y + b.z * b.z + b.w * b.w;
            *reinterpret_cast<uint4*>(smem + SMEM_B + row * ROW_BYTES + c8 * 16) =
                pack_bf16x8(a, b);
            s += __shfl_xor_sync(0xFFFFFFFFu, s, 1);
            s += __shfl_xor_sync(0xFFFFFFFFu, s, 2);
            s += __shfl_xor_sync(0xFFFFFFFFu, s, 4);
            if ((lane & 7) == 0) csq[row] = s;
        }
    }

    // --- A tile 0 into buffer 0 (+ xsq0) ---
    if (a_filler) {
        float s = pa.x * pa.x + pa.y * pa.y + pa.z * pa.z + pa.w * pa.w
                + pb.x * pb.x + pb.y * pb.y + pb.z * pb.z + pb.w * pb.w;
        *reinterpret_cast<uint4*>(smem + SMEM_A0 + a_row * ROW_BYTES + a_c8 * 16) =
            pack_bf16x8(pa, pb);
        s += __shfl_xor_sync(0xFFFFFFFFu, s, 1);
        s += __shfl_xor_sync(0xFFFFFFFFu, s, 2);
        s += __shfl_xor_sync(0xFFFFFFFFu, s, 4);
        if ((lane & 7) == 0)
            reinterpret_cast<float*>(smem + SMEM_XSQ0)[a_row] = s;
    }
    __syncthreads();   // B, csq, A0, xsq0 ready

    // --- warp tiling: wc in 0..15 (32 cols each); all warps span 32 rows ---
    const int wc = tid >> 5;

    // A fragment: row = mt*16 + lane%16, k-half = lane/16
    const uint32_t a_frag_off = (lane & 15) * ROW_BYTES + (lane >> 4) * 16;
    // B pair-x4: pair p covers n-tiles (2p, 2p+1)
    const uint32_t b_base = sb + SMEM_B +
        (wc * 32 + (lane >> 4) * 8 + (lane & 7)) * ROW_BYTES + ((lane >> 3) & 1) * 16;

#pragma unroll 1
    for (int t = 0; t < ROW_TILES; t++) {
        const int cur = t & 1;
        const int row0 = base_row0 + t * TILE_ROWS;
        const uint32_t a_base = sb + (cur ? SMEM_A1 : SMEM_A0) + a_frag_off;
        float* xsq  = reinterpret_cast<float*>(smem + (cur ? SMEM_XSQ1 : SMEM_XSQ0));
        float* rsum = reinterpret_cast<float*>(smem + (cur ? SMEM_RSUM1 : SMEM_RSUM0));

        // --- MMA: 2 m-tiles x 4 n-tiles x 4 k-steps ---
        float acc[2][4][4];
#pragma unroll
        for (int mt = 0; mt < 2; mt++)
#pragma unroll
            for (int nt = 0; nt < 4; nt++)
#pragma unroll
                for (int j = 0; j < 4; j++) acc[mt][nt][j] = 0.0f;

#pragma unroll
        for (int kt = 0; kt < 4; kt++) {
            uint32_t aA[2][4];
#pragma unroll
            for (int mt = 0; mt < 2; mt++)
                LDMATRIX_X4(aA[mt][0], aA[mt][1], aA[mt][2], aA[mt][3],
                            a_base + mt * 16 * ROW_BYTES + kt * 32);
#pragma unroll
            for (int p = 0; p < 2; p++) {
                uint32_t b0, b1, b2, b3;
                LDMATRIX_X4(b0, b1, b2, b3, b_base + p * 16 * ROW_BYTES + kt * 32);
#pragma unroll
                for (int mt = 0; mt < 2; mt++) {
                    MMA_16816_BF16(acc[mt][2*p][0],   acc[mt][2*p][1],
                                   acc[mt][2*p][2],   acc[mt][2*p][3],
                                   aA[mt][0], aA[mt][1], aA[mt][2], aA[mt][3], b0, b1);
                    MMA_16816_BF16(acc[mt][2*p+1][0], acc[mt][2*p+1][1],
                                   acc[mt][2*p+1][2], acc[mt][2*p+1][3],
                                   aA[mt][0], aA[mt][1], aA[mt][2], aA[mt][3], b2, b3);
                }
            }
        }

        // --- fill NEXT tile's A into the alternate buffer ---
        if (t + 1 < ROW_TILES && a_filler) {
            const float4* g = reinterpret_cast<const float4*>(
                x + (size_t)(row0 + TILE_ROWS + a_row) * D + a_c8 * 8);
            float4 na = g[0], nb = g[1];
            float s = na.x * na.x + na.y * na.y + na.z * na.z + na.w * na.w
                    + nb.x * nb.x + nb.y * nb.y + nb.z * nb.z + nb.w * nb.w;
            *reinterpret_cast<uint4*>(smem + (cur ? SMEM_A0 : SMEM_A1)
                                      + a_row * ROW_BYTES + a_c8 * 16) = pack_bf16x8(na, nb);
            s += __shfl_xor_sync(0xFFFFFFFFu, s, 1);
            s += __shfl_xor_sync(0xFFFFFFFFu, s, 2);
            s += __shfl_xor_sync(0xFFFFFFFFu, s, 4);
            if ((lane & 7) == 0)
                reinterpret_cast<float*>(smem + (cur ? SMEM_XSQ0 : SMEM_XSQ1))[a_row] = s;
        }

        // --- Epilogue: q = 1/(1 + x^2 + c^2 - 2 cross), paired reciprocals ---
        const int rb = lane >> 2;      // quad row within m-tile
        float xr[2][2], s_acc[2][2];
#pragma unroll
        for (int mt = 0; mt < 2; mt++)
#pragma unroll
            for (int h = 0; h < 2; h++) {
                xr[mt][h] = xsq[mt * 16 + h * 8 + rb] + 1.0f;
                s_acc[mt][h] = 0.0f;
            }

#pragma unroll
        for (int nt = 0; nt < 4; nt++) {
            const int c0 = wc * 32 + nt * 8 + (lane & 3) * 2;
            const float cs0 = csq[c0], cs1 = csq[c0 + 1];
#pragma unroll
            for (int mt = 0; mt < 2; mt++) {
                float d0 = fmaf(-2.0f, acc[mt][nt][0], xr[mt][0] + cs0);
                float d1 = fmaf(-2.0f, acc[mt][nt][1], xr[mt][0] + cs1);
                float d2 = fmaf(-2.0f, acc[mt][nt][2], xr[mt][1] + cs0);
                float d3 = fmaf(-2.0f, acc[mt][nt][3], xr[mt][1] + cs1);
                float r01 = __fdividef(1.0f, d0 * d1);
                float r23 = __fdividef(1.0f, d2 * d3);
                float q0 = r01 * d1, q1 = r01 * d0;
                float q2 = r23 * d3, q3 = r23 * d2;
                acc[mt][nt][0] = q0; acc[mt][nt][1] = q1;
                acc[mt][nt][2] = q2; acc[mt][nt][3] = q3;
                s_acc[mt][0] += q0 + q1;
                s_acc[mt][1] += q2 + q3;
            }
        }
#pragma unroll
        for (int mt = 0; mt < 2; mt++)
#pragma unroll
            for (int h = 0; h < 2; h++) {
                s_acc[mt][h] += __shfl_xor_sync(0xFFFFFFFFu, s_acc[mt][h], 1);
                s_acc[mt][h] += __shfl_xor_sync(0xFFFFFFFFu, s_acc[mt][h], 2);
            }
        if ((lane & 3) == 0) {
#pragma unroll
            for (int mt = 0; mt < 2; mt++)
#pragma unroll
                for (int h = 0; h < 2; h++)
                    rsum[wc * 32 + mt * 16 + h * 8 + rb] = s_acc[mt][h];
        }
        __syncthreads();   // rsum ready; next-A visible; buffer reuse safe

        // --- warp-local normalizers: lane L owns row L (conflict-free LDS) ---
        float srow = 0.0f;
#pragma unroll
        for (int g2 = 0; g2 < 16; g2++) srow += rsum[g2 * 32 + lane];
        const float invl = __fdividef(1.0f, srow);

        // --- normalized streaming stores (float2, 8B aligned) ---
#pragma unroll
        for (int mt = 0; mt < 2; mt++) {
            const float inv0 = __shfl_sync(0xFFFFFFFFu, invl, mt * 16 + rb);
            const float inv1 = __shfl_sync(0xFFFFFFFFu, invl, mt * 16 + rb + 8);
            float* o0 = out + (size_t)(row0 + mt * 16 + rb) * K;
            float* o1 = out + (size_t)(row0 + mt * 16 + rb + 8) * K;
#pragma unroll
            for (int nt = 0; nt < 4; nt++) {
                const int c0 = wc * 32 + nt * 8 + (lane & 3) * 2;
                __stcs(reinterpret_cast<float2*>(o0 + c0),
                       make_float2(acc[mt][nt][0] * inv0, acc[mt][nt][1] * inv0));
                __stcs(reinterpret_cast<float2*>(o1 + c0),
                       make_float2(acc[mt][nt][2] * inv1, acc[mt][nt][3] * inv1));
            }
        }
    }
}

// ====================== launch ======================
extern "C" void kernel_launch(void* const* d_in, const int* in_sizes, int n_in,
                              void* d_out, int out_size) {
    const float* x = (const float*)d_in[0];      // [N, 64] fp32
    const float* c = (const float*)d_in[1];      // [512, 64] fp32
    float* out = (float*)d_out;                  // [N, 512] fp32
    int N = in_sizes[0] / D;

    cudaFuncSetAttribute(cluster_q_kernel,
                         cudaFuncAttributeMaxDynamicSharedMemorySize, SMEM_TOTAL);
    cluster_q_kernel<<<N / (TILE_ROWS * ROW_TILES), THREADS, SMEM_TOTAL>>>(x, c, out);
}